// round 1
// baseline (speedup 1.0000x reference)
#include <cuda_runtime.h>
#include <cuda_bf16.h>
#include <math.h>

#define Bn 8
#define An 100000
#define Cn 80
#define TOPN 1000
#define MAXOBJ 100
#define CAP 4096
#define MASKW 16   // 1024 bits >= TOPN

// Histogram over float bit pattern, 1024-ULP bins, restricted to (0.05, 1.0)
static __device__ __host__ __forceinline__ unsigned bin_base() { return 0x3D4CCCCDu >> 10; }
#define BIN_BASE (0x3D4CCCCDu >> 10)                       // bits(0.05f) >> 10
#define NBINS ((int)((0x3F7FFFFFu >> 10) - BIN_BASE) + 1)  // ~36045

// ------------------- scratch (device globals; no allocation) -------------------
__device__ float              g_scores[Bn * An];
__device__ int                g_classes[Bn * An];
__device__ float4             g_boxes[Bn * An];
__device__ unsigned           g_hist[Bn * NBINS];
__device__ unsigned           g_thr[Bn];
__device__ int                g_candCount[Bn];
__device__ unsigned long long g_cand[Bn * CAP];
__device__ float              g_tscore[Bn * TOPN];
__device__ int                g_tcls[Bn * TOPN];
__device__ int                g_tvalid[Bn * TOPN];
__device__ float4             g_tbox[Bn * TOPN];
__device__ unsigned long long g_mask[Bn * TOPN * MASKW];

// ------------------- kernels -------------------

__global__ void k_zero() {
    int i = blockIdx.x * blockDim.x + threadIdx.x;
    if (i < Bn * NBINS) g_hist[i] = 0u;
    if (i < Bn) g_candCount[i] = 0;
}

// Fused: class max/argmax + box decode + score histogram
__global__ void k_decode(const float* __restrict__ cls,
                         const float4* __restrict__ reg,
                         const float4* __restrict__ anc) {
    int idx = blockIdx.x * blockDim.x + threadIdx.x;
    if (idx >= Bn * An) return;

    const float4* row = (const float4*)(cls + (size_t)idx * Cn);
    float best = -1e30f;
    int bi = 0;
#pragma unroll
    for (int j = 0; j < Cn / 4; j++) {
        float4 v = row[j];
        if (v.x > best) { best = v.x; bi = j * 4 + 0; }
        if (v.y > best) { best = v.y; bi = j * 4 + 1; }
        if (v.z > best) { best = v.z; bi = j * 4 + 2; }
        if (v.w > best) { best = v.w; bi = j * 4 + 3; }
    }
    g_scores[idx] = best;
    g_classes[idx] = bi;

    float4 r = reg[idx];   // tx, ty, tw, th
    float4 a = anc[idx];   // x1, y1, x2, y2
    float aw = __fsub_rn(a.z, a.x);
    float ah = __fsub_rn(a.w, a.y);
    float acx = __fadd_rn(a.x, __fmul_rn(0.5f, aw));
    float acy = __fadd_rn(a.y, __fmul_rn(0.5f, ah));
    float pw = __fmul_rn((float)exp((double)r.z), aw);
    float ph = __fmul_rn((float)exp((double)r.w), ah);
    float pcx = __fadd_rn(__fmul_rn(r.x, aw), acx);
    float pcy = __fadd_rn(__fmul_rn(r.y, ah), acy);
    float4 bx;
    bx.x = truncf(__fsub_rn(pcx, __fmul_rn(0.5f, pw)));
    bx.y = truncf(__fsub_rn(pcy, __fmul_rn(0.5f, ph)));
    bx.z = truncf(__fadd_rn(pcx, __fmul_rn(0.5f, pw)));
    bx.w = truncf(__fadd_rn(pcy, __fmul_rn(0.5f, ph)));
    g_boxes[idx] = bx;

    if (best > 0.05f) {
        unsigned bits = __float_as_uint(best);
        int bin = (int)((bits >> 10) - BIN_BASE);
        bin = max(0, min(NBINS - 1, bin));
        atomicAdd(&g_hist[(idx / An) * NBINS + bin], 1u);
    }
}

// Per-image: scan histogram from the top to find the bin where cum >= TOPN
__global__ void k_thresh() {
    int b = blockIdx.x;
    __shared__ unsigned vals[256];
    __shared__ int s_cum, s_done;
    __shared__ unsigned s_thr;
    if (threadIdx.x == 0) { s_cum = 0; s_done = 0; s_thr = 0u; }
    __syncthreads();
    int nch = (NBINS + 255) / 256;
    for (int ci = nch - 1; ci >= 0; --ci) {
        int bin = ci * 256 + threadIdx.x;
        vals[threadIdx.x] = (bin < NBINS) ? g_hist[b * NBINS + bin] : 0u;
        __syncthreads();
        if (threadIdx.x == 0) {
            int sum = 0;
            for (int k = 0; k < 256; k++) sum += (int)vals[k];
            if (s_cum + sum >= TOPN) {
                int cum = s_cum;
                for (int k = 255; k >= 0; --k) {
                    cum += (int)vals[k];
                    if (cum >= TOPN) {
                        s_thr = (BIN_BASE + (unsigned)(ci * 256 + k)) << 10;
                        break;
                    }
                }
                s_done = 1;
            } else {
                s_cum += sum;
            }
        }
        __syncthreads();
        if (s_done) break;
    }
    if (threadIdx.x == 0) g_thr[b] = s_thr;  // 0 => take everything above MIN_SCORE
}

__global__ void k_collect() {
    int idx = blockIdx.x * blockDim.x + threadIdx.x;
    if (idx >= Bn * An) return;
    float s = g_scores[idx];
    if (s > 0.05f) {
        int b = idx / An;
        unsigned bits = __float_as_uint(s);
        if (bits >= g_thr[b]) {
            int pos = atomicAdd(&g_candCount[b], 1);
            if (pos < CAP) {
                unsigned a = (unsigned)(idx - b * An);
                g_cand[b * CAP + pos] =
                    ((unsigned long long)bits << 32) | (unsigned long long)(~a);
            }
        }
    }
}

// Per-image bitonic sort (descending) of up to CAP candidate keys; gather top-1000
__global__ void k_sort() {
    int b = blockIdx.x, t = threadIdx.x;
    __shared__ unsigned long long key[CAP];
    int cnt = min(g_candCount[b], CAP);
    for (int i = t; i < CAP; i += blockDim.x)
        key[i] = (i < cnt) ? g_cand[b * CAP + i] : 0ull;
    __syncthreads();
    for (int k = 2; k <= CAP; k <<= 1) {
        for (int j = k >> 1; j > 0; j >>= 1) {
            for (int i = t; i < CAP; i += blockDim.x) {
                int ixj = i ^ j;
                if (ixj > i) {
                    unsigned long long x = key[i], y = key[ixj];
                    bool desc = ((i & k) == 0);
                    if ((x < y) == desc) { key[i] = y; key[ixj] = x; }
                }
            }
            __syncthreads();
        }
    }
    for (int i = t; i < TOPN; i += blockDim.x) {
        unsigned long long kk = key[i];
        int o = b * TOPN + i;
        if (kk) {
            unsigned bits = (unsigned)(kk >> 32);
            unsigned a = ~(unsigned)kk;
            int src = b * An + (int)a;
            g_tscore[o] = __uint_as_float(bits);
            g_tcls[o]   = g_classes[src];
            g_tvalid[o] = 1;
            g_tbox[o]   = g_boxes[src];
        } else {
            g_tscore[o] = -1.f;
            g_tcls[o]   = -1;
            g_tvalid[o] = 0;
            g_tbox[o]   = make_float4(0.f, 0.f, 0.f, 0.f);
        }
    }
}

// 1000x1000 IoU suppression mask (bit set: j suppressed by i, j > i, iou >= 0.5)
__global__ void k_mask() {
    int b = blockIdx.z, rb = blockIdx.y, cb = blockIdx.x, t = threadIdx.x;
    __shared__ float4 cbox[64];
    __shared__ float carea[64];
    int j0 = cb * 64;
    int j = j0 + t;
    float4 bj = (j < TOPN) ? g_tbox[b * TOPN + j] : make_float4(0.f, 0.f, 0.f, 0.f);
    cbox[t] = bj;
    carea[t] = fmaxf((bj.z - bj.x) * (bj.w - bj.y), 1e-4f);
    __syncthreads();
    int i = rb * 64 + t;
    if (i < TOPN) {
        float4 bi = g_tbox[b * TOPN + i];
        float ai = fmaxf((bi.z - bi.x) * (bi.w - bi.y), 1e-4f);
        unsigned long long bits = 0ull;
        for (int jj = 0; jj < 64; jj++) {
            int jg = j0 + jj;
            if (jg > i && jg < TOPN) {
                float4 bb = cbox[jj];
                float tlx = fmaxf(bi.x, bb.x), tly = fmaxf(bi.y, bb.y);
                float brx = fminf(bi.z, bb.z), bry = fminf(bi.w, bb.w);
                float iw = fmaxf(brx - tlx, 0.f), ih = fmaxf(bry - tly, 0.f);
                float inter = iw * ih;
                float un = fmaxf(ai + carea[jj] - inter, 1e-4f);
                if (inter / un >= 0.5f) bits |= (1ull << jj);
            }
        }
        g_mask[(b * TOPN + i) * MASKW + cb] = bits;
    }
}

// Serial greedy scan over mask (staged in shared), compact first MAXOBJ, write outputs
__global__ void k_final(float* __restrict__ out) {
    int b = blockIdx.x, t = threadIdx.x;
    extern __shared__ unsigned long long sm[];
    unsigned long long* smask = sm;             // TOPN*MASKW
    unsigned long long* srem = sm + TOPN * MASKW;  // MASKW

    for (int i = t; i < TOPN * MASKW; i += blockDim.x)
        smask[i] = g_mask[b * TOPN * MASKW + i];
    if (t < MASKW) {
        unsigned long long w = 0ull;
        for (int k = 0; k < 64; k++) {
            int i = t * 64 + k;
            if (i >= TOPN || !g_tvalid[b * TOPN + i]) w |= (1ull << k);
        }
        srem[t] = w;
    }
    float* out_s = out;
    float* out_c = out + Bn * MAXOBJ;
    float* out_b = out + 2 * Bn * MAXOBJ;
    for (int k = t; k < MAXOBJ; k += blockDim.x) {
        out_s[b * MAXOBJ + k] = -1.f;
        out_c[b * MAXOBJ + k] = -1.f;
        ((float4*)out_b)[b * MAXOBJ + k] = make_float4(0.f, 0.f, 0.f, 0.f);
    }
    __syncthreads();

    if (t == 0) {
        unsigned long long rem[MASKW];
#pragma unroll
        for (int w = 0; w < MASKW; w++) rem[w] = srem[w];
        int nk = 0;
        for (int i = 0; i < TOPN && nk < MAXOBJ; i++) {
            if ((rem[i >> 6] >> (i & 63)) & 1ull) continue;
            int o = b * TOPN + i;
            out_s[b * MAXOBJ + nk] = g_tscore[o];
            out_c[b * MAXOBJ + nk] = (float)g_tcls[o];
            ((float4*)out_b)[b * MAXOBJ + nk] = g_tbox[o];
            nk++;
#pragma unroll
            for (int w = 0; w < MASKW; w++) rem[w] |= smask[i * MASKW + w];
        }
    }
}

// ------------------- launch -------------------
extern "C" void kernel_launch(void* const* d_in, const int* in_sizes, int n_in,
                              void* d_out, int out_size) {
    const float*  cls = (const float*)d_in[0];
    const float4* reg = (const float4*)d_in[1];
    const float4* anc = (const float4*)d_in[2];
    float* out = (float*)d_out;

    const int FINAL_SMEM = (TOPN * MASKW + MASKW) * (int)sizeof(unsigned long long);
    cudaFuncSetAttribute(k_final, cudaFuncAttributeMaxDynamicSharedMemorySize, FINAL_SMEM);

    int nzero = Bn * NBINS;
    k_zero<<<(nzero + 255) / 256, 256>>>();
    int total = Bn * An;
    k_decode<<<(total + 255) / 256, 256>>>(cls, reg, anc);
    k_thresh<<<Bn, 256>>>();
    k_collect<<<(total + 255) / 256, 256>>>();
    k_sort<<<Bn, 1024>>>();
    k_mask<<<dim3((TOPN + 63) / 64, (TOPN + 63) / 64, Bn), 64>>>();
    k_final<<<Bn, 256, FINAL_SMEM>>>(out);
}